// round 5
// baseline (speedup 1.0000x reference)
#include <cuda_runtime.h>
#include <cuda_bf16.h>

#define N_NODES_C 40000
#define N_EDGES_C 640000
#define DIM 128
#define SCAN_BLOCKS ((N_NODES_C + 255) / 256)   // 157

// scratch
__device__ float g_h[N_NODES_C * DIM];       // relu(x@W+b)
__device__ int   g_scol[N_EDGES_C];          // cols bucketed by dst row
__device__ int   g_cnt[N_NODES_C];
__device__ int   g_offs[N_NODES_C + 1];
__device__ int   g_cursor[N_NODES_C];
__device__ int   g_blksum[SCAN_BLOCKS];

// Side stream + events for fork-join graph capture (created once at load;
// no device-memory allocation, no per-call guards).
struct ForkCtx {
    cudaStream_t side;
    cudaEvent_t  ev_fork, ev_join;
    ForkCtx() {
        cudaStreamCreateWithFlags(&side, cudaStreamNonBlocking);
        cudaEventCreateWithFlags(&ev_fork, cudaEventDisableTiming);
        cudaEventCreateWithFlags(&ev_join, cudaEventDisableTiming);
    }
};
static ForkCtx g_fork;

// ---------------------------------------------------------------------------
// P0: zero histogram counters
// ---------------------------------------------------------------------------
__global__ void init_kernel() {
    int i = blockIdx.x * blockDim.x + threadIdx.x;
    if (i < N_NODES_C) g_cnt[i] = 0;
}

// ---------------------------------------------------------------------------
// P1: histogram of destination rows (edge_index is int32: row[e]=ei[e])
// ---------------------------------------------------------------------------
__global__ void hist_kernel(const int* __restrict__ ei32) {
    int i = blockIdx.x * blockDim.x + threadIdx.x;
    if (i < N_EDGES_C) atomicAdd(&g_cnt[ei32[i]], 1);
}

// ---------------------------------------------------------------------------
// P2: per-block sums of g_cnt
// ---------------------------------------------------------------------------
__global__ __launch_bounds__(256)
void scan_blocksum_kernel() {
    __shared__ int sd[256];
    int i = blockIdx.x * 256 + threadIdx.x;
    sd[threadIdx.x] = (i < N_NODES_C) ? g_cnt[i] : 0;
    __syncthreads();
    #pragma unroll
    for (int s = 128; s > 0; s >>= 1) {
        if (threadIdx.x < s) sd[threadIdx.x] += sd[threadIdx.x + s];
        __syncthreads();
    }
    if (threadIdx.x == 0) g_blksum[blockIdx.x] = sd[0];
}

// ---------------------------------------------------------------------------
// P3: each block computes its own prefix over blksum, then scans its chunk
// ---------------------------------------------------------------------------
__global__ __launch_bounds__(256)
void scan_write_kernel() {
    __shared__ int sd[256];
    __shared__ int warp_part[8];
    const int t = threadIdx.x;

    // block offset = sum of blksum[0..blockIdx.x)
    int part = 0;
    for (int j = t; j < blockIdx.x; j += 256) part += g_blksum[j];
    #pragma unroll
    for (int d = 16; d > 0; d >>= 1)
        part += __shfl_xor_sync(0xFFFFFFFFu, part, d);
    if ((t & 31) == 0) warp_part[t >> 5] = part;

    const int i = blockIdx.x * 256 + t;
    const int v = (i < N_NODES_C) ? g_cnt[i] : 0;
    sd[t] = v;
    __syncthreads();

    int boff = 0;
    #pragma unroll
    for (int wnum = 0; wnum < 8; wnum++) boff += warp_part[wnum];

    // Hillis-Steele inclusive scan over the chunk
    #pragma unroll
    for (int off = 1; off < 256; off <<= 1) {
        int u = (t >= off) ? sd[t - off] : 0;
        __syncthreads();
        sd[t] += u;
        __syncthreads();
    }

    if (i < N_NODES_C) {
        int excl = boff + sd[t] - v;
        g_offs[i]   = excl;
        g_cursor[i] = excl;
    }
    if (i == 0) g_offs[N_NODES_C] = N_EDGES_C;
}

// ---------------------------------------------------------------------------
// P4: bucket source cols by destination row
// ---------------------------------------------------------------------------
__global__ void bucket_kernel(const int* __restrict__ ei32) {
    int i = blockIdx.x * blockDim.x + threadIdx.x;
    if (i >= N_EDGES_C) return;
    int p = atomicAdd(&g_cursor[ei32[i]], 1);
    g_scol[p] = ei32[N_EDGES_C + i];
}

// ---------------------------------------------------------------------------
// G: h = relu(x @ W + b) using packed fma.rn.f32x2 along k (even/odd halves).
//    Block = 8 warps -> 64 rows; warp -> 8 rows; lane -> 4 cols (2 f32x2).
// ---------------------------------------------------------------------------
__global__ __launch_bounds__(256)
void gemm_bias_relu_kernel(const float* __restrict__ x,
                           const float* __restrict__ w,
                           const float* __restrict__ bias,
                           float* __restrict__ h) {
    __shared__ float Xs[64 * DIM];   // 32 KB

    const int tid  = threadIdx.x;
    const int row0 = blockIdx.x * 64;

    const float4* xg = (const float4*)(x + (size_t)row0 * DIM);
    float4* xs4 = (float4*)Xs;
    #pragma unroll
    for (int i = 0; i < 8; i++)
        xs4[tid + i * 256] = xg[tid + i * 256];
    __syncthreads();

    const int warp = tid >> 5;
    const int lane = tid & 31;

    unsigned long long acc[8][4];
    #pragma unroll
    for (int r = 0; r < 8; r++)
        #pragma unroll
        for (int j = 0; j < 4; j++) acc[r][j] = 0ULL;

    const float* xrow = Xs + warp * 8 * DIM;
    const float4* wrow = (const float4*)w;   // w[k][n] row-major, 32 float4/row

    #pragma unroll 2
    for (int k = 0; k < DIM; k += 2) {
        float4 wa = __ldg(&wrow[k * 32 + lane]);
        float4 wb = __ldg(&wrow[(k + 1) * 32 + lane]);
        unsigned long long w0, w1, w2, w3;
        asm("mov.b64 %0, {%1, %2};" : "=l"(w0) : "f"(wa.x), "f"(wb.x));
        asm("mov.b64 %0, {%1, %2};" : "=l"(w1) : "f"(wa.y), "f"(wb.y));
        asm("mov.b64 %0, {%1, %2};" : "=l"(w2) : "f"(wa.z), "f"(wb.z));
        asm("mov.b64 %0, {%1, %2};" : "=l"(w3) : "f"(wa.w), "f"(wb.w));
        #pragma unroll
        for (int r = 0; r < 8; r++) {
            unsigned long long xv =
                *(const unsigned long long*)(xrow + r * DIM + k);
            asm("fma.rn.f32x2 %0, %1, %2, %0;" : "+l"(acc[r][0]) : "l"(xv), "l"(w0));
            asm("fma.rn.f32x2 %0, %1, %2, %0;" : "+l"(acc[r][1]) : "l"(xv), "l"(w1));
            asm("fma.rn.f32x2 %0, %1, %2, %0;" : "+l"(acc[r][2]) : "l"(xv), "l"(w2));
            asm("fma.rn.f32x2 %0, %1, %2, %0;" : "+l"(acc[r][3]) : "l"(xv), "l"(w3));
        }
    }

    float4 b4 = __ldg(&((const float4*)bias)[lane]);
    #pragma unroll
    for (int r = 0; r < 8; r++) {
        int row = row0 + warp * 8 + r;
        float lo, hi;
        float4 o;
        asm("mov.b64 {%0, %1}, %2;" : "=f"(lo), "=f"(hi) : "l"(acc[r][0]));
        o.x = fmaxf(lo + hi + b4.x, 0.f);
        asm("mov.b64 {%0, %1}, %2;" : "=f"(lo), "=f"(hi) : "l"(acc[r][1]));
        o.y = fmaxf(lo + hi + b4.y, 0.f);
        asm("mov.b64 {%0, %1}, %2;" : "=f"(lo), "=f"(hi) : "l"(acc[r][2]));
        o.z = fmaxf(lo + hi + b4.z, 0.f);
        asm("mov.b64 {%0, %1}, %2;" : "=f"(lo), "=f"(hi) : "l"(acc[r][3]));
        o.w = fmaxf(lo + hi + b4.w, 0.f);
        ((float4*)(h + (size_t)row * DIM))[lane] = o;
    }
}

// ---------------------------------------------------------------------------
// A: aggregate. One warp per node; lane covers 4 feats. Cols staged 32 at a
//    time via shfl so the h-gathers are independent (high MLP).
// ---------------------------------------------------------------------------
__global__ __launch_bounds__(256)
void aggregate_kernel(const float* __restrict__ h,
                      float* __restrict__ out) {
    int node = (int)((blockIdx.x * (long long)blockDim.x + threadIdx.x) >> 5);
    int lane = threadIdx.x & 31;
    if (node >= N_NODES_C) return;

    int beg = g_offs[node];
    int end = g_offs[node + 1];

    float4 acc = make_float4(0.f, 0.f, 0.f, 0.f);

    for (int base = beg; base < end; base += 32) {
        int myc = (base + lane < end) ? g_scol[base + lane] : 0;
        int cnt = min(32, end - base);
        #pragma unroll 4
        for (int j = 0; j < cnt; j++) {
            int c = __shfl_sync(0xFFFFFFFFu, myc, j);
            float4 v = __ldg(&((const float4*)(h + (size_t)c * DIM))[lane]);
            acc.x = fmaxf(acc.x, v.x);
            acc.y = fmaxf(acc.y, v.y);
            acc.z = fmaxf(acc.z, v.z);
            acc.w = fmaxf(acc.w, v.w);
        }
    }

    ((float4*)(out + (size_t)node * DIM))[lane] = acc;
}

// ---------------------------------------------------------------------------
extern "C" void kernel_launch(void* const* d_in, const int* in_sizes, int n_in,
                              void* d_out, int out_size) {
    const float* x    = (const float*)d_in[0];
    const int*   ei32 = (const int*)d_in[1];   // int32 (verified: R1 int64 read crashed)
    const float* w    = (const float*)d_in[2];
    const float* bias = (const float*)d_in[3];
    float*       out  = (float*)d_out;

    float* h;
    cudaGetSymbolAddress((void**)&h, g_h);

    // Fork: GEMM on side stream, edge-prep on main stream.
    cudaEventRecord(g_fork.ev_fork, 0);
    cudaStreamWaitEvent(g_fork.side, g_fork.ev_fork, 0);
    gemm_bias_relu_kernel<<<N_NODES_C / 64, 256, 0, g_fork.side>>>(x, w, bias, h);
    cudaEventRecord(g_fork.ev_join, g_fork.side);

    // Edge prep on main stream
    init_kernel<<<(N_NODES_C + 255) / 256, 256>>>();
    hist_kernel<<<(N_EDGES_C + 255) / 256, 256>>>(ei32);
    scan_blocksum_kernel<<<SCAN_BLOCKS, 256>>>();
    scan_write_kernel<<<SCAN_BLOCKS, 256>>>();
    bucket_kernel<<<(N_EDGES_C + 255) / 256, 256>>>(ei32);

    // Join: aggregate needs both h and CSR.
    cudaStreamWaitEvent(0, g_fork.ev_join, 0);
    aggregate_kernel<<<(N_NODES_C * 32 + 255) / 256, 256>>>(h, out);
}

// round 6
// speedup vs baseline: 1.6498x; 1.6498x over previous
#include <cuda_runtime.h>
#include <cuda_bf16.h>

#define N_NODES_C 40000
#define N_EDGES_C 640000
#define DIM 128
#define SCAN_BLOCKS ((N_NODES_C + 255) / 256)   // 157

// scratch
__device__ float g_h[N_NODES_C * DIM];       // relu(x@W+b)
__device__ int   g_scol[N_EDGES_C];          // cols bucketed by dst row
__device__ int   g_cnt[N_NODES_C];
__device__ int   g_offs[N_NODES_C + 1];
__device__ int   g_cursor[N_NODES_C];
__device__ int   g_blksum[SCAN_BLOCKS];

// Side stream + events for fork-join graph capture (created once at load).
struct ForkCtx {
    cudaStream_t side;
    cudaEvent_t  ev_fork, ev_join;
    ForkCtx() {
        cudaStreamCreateWithFlags(&side, cudaStreamNonBlocking);
        cudaEventCreateWithFlags(&ev_fork, cudaEventDisableTiming);
        cudaEventCreateWithFlags(&ev_join, cudaEventDisableTiming);
    }
};
static ForkCtx g_fork;

// ---------------------------------------------------------------------------
// P0: zero histogram counters
// ---------------------------------------------------------------------------
__global__ void init_kernel() {
    int i = blockIdx.x * blockDim.x + threadIdx.x;
    if (i < N_NODES_C) g_cnt[i] = 0;
}

// ---------------------------------------------------------------------------
// P1: histogram of destination rows (edge_index is int32: row[e]=ei[e])
// ---------------------------------------------------------------------------
__global__ void hist_kernel(const int* __restrict__ ei32) {
    int i = blockIdx.x * blockDim.x + threadIdx.x;
    if (i < N_EDGES_C) atomicAdd(&g_cnt[ei32[i]], 1);
}

// ---------------------------------------------------------------------------
// P2: per-block sums of g_cnt
// ---------------------------------------------------------------------------
__global__ __launch_bounds__(256)
void scan_blocksum_kernel() {
    __shared__ int sd[256];
    int i = blockIdx.x * 256 + threadIdx.x;
    sd[threadIdx.x] = (i < N_NODES_C) ? g_cnt[i] : 0;
    __syncthreads();
    #pragma unroll
    for (int s = 128; s > 0; s >>= 1) {
        if (threadIdx.x < s) sd[threadIdx.x] += sd[threadIdx.x + s];
        __syncthreads();
    }
    if (threadIdx.x == 0) g_blksum[blockIdx.x] = sd[0];
}

// ---------------------------------------------------------------------------
// P3: each block computes its own prefix over blksum, then scans its chunk
// ---------------------------------------------------------------------------
__global__ __launch_bounds__(256)
void scan_write_kernel() {
    __shared__ int sd[256];
    __shared__ int warp_part[8];
    const int t = threadIdx.x;

    // block offset = sum of blksum[0..blockIdx.x)
    int part = 0;
    for (int j = t; j < blockIdx.x; j += 256) part += g_blksum[j];
    #pragma unroll
    for (int d = 16; d > 0; d >>= 1)
        part += __shfl_xor_sync(0xFFFFFFFFu, part, d);
    if ((t & 31) == 0) warp_part[t >> 5] = part;

    const int i = blockIdx.x * 256 + t;
    const int v = (i < N_NODES_C) ? g_cnt[i] : 0;
    sd[t] = v;
    __syncthreads();

    int boff = 0;
    #pragma unroll
    for (int wnum = 0; wnum < 8; wnum++) boff += warp_part[wnum];

    // Hillis-Steele inclusive scan over the chunk
    #pragma unroll
    for (int off = 1; off < 256; off <<= 1) {
        int u = (t >= off) ? sd[t - off] : 0;
        __syncthreads();
        sd[t] += u;
        __syncthreads();
    }

    if (i < N_NODES_C) {
        int excl = boff + sd[t] - v;
        g_offs[i]   = excl;
        g_cursor[i] = excl;
    }
    if (i == 0) g_offs[N_NODES_C] = N_EDGES_C;
}

// ---------------------------------------------------------------------------
// P4: bucket source cols by destination row
// ---------------------------------------------------------------------------
__global__ void bucket_kernel(const int* __restrict__ ei32) {
    int i = blockIdx.x * blockDim.x + threadIdx.x;
    if (i >= N_EDGES_C) return;
    int p = atomicAdd(&g_cursor[ei32[i]], 1);
    g_scol[p] = ei32[N_EDGES_C + i];
}

// ---------------------------------------------------------------------------
// G: h = relu(x @ W + b). Plain FFMA (proven R4 version: rel_err 0.0,
//    ~35us). Block = 8 warps -> 64 rows; warp -> 8 rows; lane -> 4 cols.
// ---------------------------------------------------------------------------
__global__ __launch_bounds__(256)
void gemm_bias_relu_kernel(const float* __restrict__ x,
                           const float* __restrict__ w,
                           const float* __restrict__ bias,
                           float* __restrict__ h) {
    __shared__ float Xs[64 * DIM];   // 32 KB

    const int tid  = threadIdx.x;
    const int row0 = blockIdx.x * 64;

    const float4* xg = (const float4*)(x + (size_t)row0 * DIM);
    float4* xs4 = (float4*)Xs;
    #pragma unroll
    for (int i = 0; i < 8; i++)
        xs4[tid + i * 256] = xg[tid + i * 256];
    __syncthreads();

    const int warp = tid >> 5;
    const int lane = tid & 31;

    float acc[8][4];
    #pragma unroll
    for (int r = 0; r < 8; r++)
        #pragma unroll
        for (int j = 0; j < 4; j++) acc[r][j] = 0.f;

    const float* xrow = Xs + warp * 8 * DIM;
    const float4* wrow = (const float4*)w;

    #pragma unroll 4
    for (int k = 0; k < DIM; k++) {
        float4 w4 = __ldg(&wrow[k * 32 + lane]);
        #pragma unroll
        for (int r = 0; r < 8; r++) {
            float xv = xrow[r * DIM + k];
            acc[r][0] = fmaf(xv, w4.x, acc[r][0]);
            acc[r][1] = fmaf(xv, w4.y, acc[r][1]);
            acc[r][2] = fmaf(xv, w4.z, acc[r][2]);
            acc[r][3] = fmaf(xv, w4.w, acc[r][3]);
        }
    }

    float4 b4 = __ldg(&((const float4*)bias)[lane]);
    #pragma unroll
    for (int r = 0; r < 8; r++) {
        int row = row0 + warp * 8 + r;
        float4 o;
        o.x = fmaxf(acc[r][0] + b4.x, 0.f);
        o.y = fmaxf(acc[r][1] + b4.y, 0.f);
        o.z = fmaxf(acc[r][2] + b4.z, 0.f);
        o.w = fmaxf(acc[r][3] + b4.w, 0.f);
        ((float4*)(h + (size_t)row * DIM))[lane] = o;
    }
}

// ---------------------------------------------------------------------------
// A: aggregate. One warp per node; lane covers 4 feats. Cols staged 32 at a
//    time via shfl so the h-gathers are independent (high MLP).
// ---------------------------------------------------------------------------
__global__ __launch_bounds__(256)
void aggregate_kernel(const float* __restrict__ h,
                      float* __restrict__ out) {
    int node = (int)((blockIdx.x * (long long)blockDim.x + threadIdx.x) >> 5);
    int lane = threadIdx.x & 31;
    if (node >= N_NODES_C) return;

    int beg = g_offs[node];
    int end = g_offs[node + 1];

    float4 acc = make_float4(0.f, 0.f, 0.f, 0.f);

    for (int base = beg; base < end; base += 32) {
        int myc = (base + lane < end) ? g_scol[base + lane] : 0;
        int cnt = min(32, end - base);
        #pragma unroll 4
        for (int j = 0; j < cnt; j++) {
            int c = __shfl_sync(0xFFFFFFFFu, myc, j);
            float4 v = __ldg(&((const float4*)(h + (size_t)c * DIM))[lane]);
            acc.x = fmaxf(acc.x, v.x);
            acc.y = fmaxf(acc.y, v.y);
            acc.z = fmaxf(acc.z, v.z);
            acc.w = fmaxf(acc.w, v.w);
        }
    }

    ((float4*)(out + (size_t)node * DIM))[lane] = acc;
}

// ---------------------------------------------------------------------------
extern "C" void kernel_launch(void* const* d_in, const int* in_sizes, int n_in,
                              void* d_out, int out_size) {
    const float* x    = (const float*)d_in[0];
    const int*   ei32 = (const int*)d_in[1];   // int32 (verified in R1/R2)
    const float* w    = (const float*)d_in[2];
    const float* bias = (const float*)d_in[3];
    float*       out  = (float*)d_out;

    float* h;
    cudaGetSymbolAddress((void**)&h, g_h);

    // Fork: GEMM on side stream, edge-prep on main stream.
    cudaEventRecord(g_fork.ev_fork, 0);
    cudaStreamWaitEvent(g_fork.side, g_fork.ev_fork, 0);
    gemm_bias_relu_kernel<<<N_NODES_C / 64, 256, 0, g_fork.side>>>(x, w, bias, h);
    cudaEventRecord(g_fork.ev_join, g_fork.side);

    // Edge prep on main stream
    init_kernel<<<(N_NODES_C + 255) / 256, 256>>>();
    hist_kernel<<<(N_EDGES_C + 255) / 256, 256>>>(ei32);
    scan_blocksum_kernel<<<SCAN_BLOCKS, 256>>>();
    scan_write_kernel<<<SCAN_BLOCKS, 256>>>();
    bucket_kernel<<<(N_EDGES_C + 255) / 256, 256>>>(ei32);

    // Join: aggregate needs both h and CSR.
    cudaStreamWaitEvent(0, g_fork.ev_join, 0);
    aggregate_kernel<<<(N_NODES_C * 32 + 255) / 256, 256>>>(h, out);
}